// round 14
// baseline (speedup 1.0000x reference)
#include <cuda_runtime.h>
#include <cstdint>

// QCNN_58025008169535
// x: [32,128,128,3] f32, w: [4,4,3] f32 -> out: [32, 127*127, 4] f32
//
// Tensor-core formulation. amp_re = A0 v, amp_im = A0 v', where
// A0 = [ReU | -ImU] (16x32), v = [Re psi; Im psi], v' = [Im psi; -Re psi]
// (v' fragments = v fragments, k-tiles rotated by 2, sign-flipped t>=2).
// 2-pass tf32 split (Ahi+Alo)*Btf32; B staged as tf32 bits at encode.
// R14: single fused kernel. Block 0 builds U (every launch, deterministic),
// publishes via device flag; other blocks spin only on the first launch.

#define DIM 16
#define NQ 4

static constexpr int Bc = 32, Hc = 128, Wc = 128;
static constexpr int PHc = Hc - 1, PWc = Wc - 1;
static constexpr int Pc = PHc * PWc;          // 16129
static constexpr int TOTALc = Bc * Pc;        // 516128
static constexpr int WTOT = TOTALc / 32;      // 16129 warp-iterations
static constexpr int TITER = 2;               // warp-iters per warp
static constexpr int NWARP = 4;               // warps per block
static constexpr int NBLK = (WTOT + NWARP * TITER - 1) / (NWARP * TITER);  // 2017

typedef unsigned int uint;

__device__ float g_Whi[32 * 32];
__device__ float g_Wlo[32 * 32];
__device__ int   g_flag = 0;     // one-way latch; U is identical every launch

__device__ __forceinline__ float2 cmul(float2 a, float2 b) {
    return make_float2(fmaf(a.x, b.x, -a.y * b.y), fmaf(a.x, b.y, a.y * b.x));
}
__device__ __forceinline__ float2 cadd(float2 a, float2 b) {
    return make_float2(a.x + b.x, a.y + b.y);
}
__device__ __forceinline__ uint tf32cvt(float f) {
    uint r; asm("cvt.rna.tf32.f32 %0, %1;" : "=r"(r) : "f"(f)); return r;
}

#define MMA_TF32(C0, C1, C2, C3, A0, A1, A2, A3, B0, B1)                      \
    asm volatile(                                                             \
        "mma.sync.aligned.m16n8k8.row.col.f32.tf32.tf32.f32 "                 \
        "{%0,%1,%2,%3}, {%4,%5,%6,%7}, {%8,%9}, {%0,%1,%2,%3};"               \
        : "+f"(C0), "+f"(C1), "+f"(C2), "+f"(C3)                              \
        : "r"(A0), "r"(A1), "r"(A2), "r"(A3), "r"(B0), "r"(B1))

// ---------------------------------------------------------------------------
// Build the variational unitary with 128 threads on shared scratch.
// Scratch layout: sg 512B | sM 8192B | sT 4096B  (12800B total).
// ---------------------------------------------------------------------------
__device__ void build_U(const float* __restrict__ w, char* scratch, int tid) {
    float2 (*sg)[4]      = reinterpret_cast<float2(*)[4]>(scratch);
    float2 (*sM)[16][16] = reinterpret_cast<float2(*)[16][16]>(scratch + 512);
    float2 (*sT)[16][16] = reinterpret_cast<float2(*)[16][16]>(scratch + 512 + 8192);

    if (tid < 16) {
        float wx = w[tid * 3 + 0];
        float wy = w[tid * 3 + 1];
        float wz = w[tid * 3 + 2];
        float cx, sx, cy, sy, cz, sz;
        sincosf(0.5f * wx, &sx, &cx);
        sincosf(0.5f * wy, &sy, &cy);
        sincosf(0.5f * wz, &sz, &cz);
        float2 m00 = make_float2(cy * cx,  sy * sx);
        float2 m01 = make_float2(-sy * cx, -cy * sx);
        float2 m10 = make_float2(sy * cx,  -cy * sx);
        float2 m11 = make_float2(cy * cx,  -sy * sx);
        float2 e0 = make_float2(cz, -sz);
        float2 e1 = make_float2(cz,  sz);
        sg[tid][0] = cmul(e0, m00);
        sg[tid][1] = cmul(e0, m01);
        sg[tid][2] = cmul(e1, m10);
        sg[tid][3] = cmul(e1, m11);
    }
    __syncthreads();

    // Layer matrices: 1024 elements, 8 per thread
#pragma unroll
    for (int r = 0; r < 8; r++) {
        int e = tid + 128 * r;
        int h = e >> 8;
        int st = e & 255;
        int s = st >> 4, t = st & 15;
        float2 prod = make_float2(1.f, 0.f);
#pragma unroll
        for (int q = 0; q < NQ; q++) {
            int sb = (s >> (3 - q)) & 1;
            int tb = (t >> (3 - q)) & 1;
            prod = cmul(prod, sg[h * 4 + q][sb * 2 + tb]);
        }
        bool neg = (((s & 12) == 12) ^ ((s & 3) == 3)) ^ ((s & 6) == 6);
        if (neg) { prod.x = -prod.x; prod.y = -prod.y; }
        sM[h][s][t] = prod;
    }
    __syncthreads();

    // T1 = M2*M1, T2 = M4*M3: 256 elems, 2 per thread
#pragma unroll
    for (int r = 0; r < 2; r++) {
        int e = tid + 128 * r;
        int s = e >> 4, t = e & 15;
        float2 a1 = make_float2(0.f, 0.f);
        float2 a2 = make_float2(0.f, 0.f);
#pragma unroll
        for (int k = 0; k < DIM; k++) {
            a1 = cadd(a1, cmul(sM[1][s][k], sM[0][k][t]));
            a2 = cadd(a2, cmul(sM[3][s][k], sM[2][k][t]));
        }
        sT[0][s][t] = a1;
        sT[1][s][t] = a2;
    }
    __syncthreads();

    // U = T2*T1; emit W = [[Re,-Im],[Im,Re]] (hi/lo tf32 split)
#pragma unroll
    for (int r = 0; r < 2; r++) {
        int e = tid + 128 * r;
        int s = e >> 4, t = e & 15;
        float2 u = make_float2(0.f, 0.f);
#pragma unroll
        for (int k = 0; k < DIM; k++)
            u = cadd(u, cmul(sT[1][s][k], sT[0][k][t]));

        float vals[4] = {u.x, -u.y, u.y, u.x};
        int   idxs[4] = {s * 32 + t, s * 32 + 16 + t,
                         (16 + s) * 32 + t, (16 + s) * 32 + 16 + t};
#pragma unroll
        for (int q = 0; q < 4; q++) {
            float f  = vals[q];
            uint  hb = tf32cvt(f);
            float hf = __uint_as_float(hb);
            uint  lb = tf32cvt(f - hf);
            g_Whi[idxs[q]] = hf;
            g_Wlo[idxs[q]] = __uint_as_float(lb);
        }
    }
    __syncthreads();
}

// ---------------------------------------------------------------------------
// Load (l1,l2) of the 4 patch pixels for patch index idx.
// ---------------------------------------------------------------------------
__device__ __forceinline__ void load_px(const float* __restrict__ x, int idx,
                                        float2* pre) {
    int b  = idx / Pc;
    int p  = idx - b * Pc;
    int ph = p / PWc;
    int pw = p - ph * PWc;
    const float* base = x + (((b * Hc) + ph) * Wc + pw) * 3;
#pragma unroll
    for (int n = 0; n < 4; n++) {
        int dy = n >> 1, dx = n & 1;
        const float* px = base + (dy * Wc + dx) * 3;
        pre[n] = make_float2(__ldg(px + 1), __ldg(px + 2));
    }
}

struct Acc { float c0, c1, c2, c3, d0, d1, d2, d3; };

__global__ void __launch_bounds__(128, 7)
k_qcnn(const float* __restrict__ x, const float* __restrict__ w,
       float* __restrict__ out) {
    __shared__ __align__(16) uint v_sm[NWARP][32][36];   // 18KB (build scratch aliased)

    int tid  = threadIdx.x;
    int wrp  = tid >> 5;
    int lane = tid & 31;
    int g    = lane >> 2;
    int mm   = lane & 3;

    // ---- block 0: rebuild U (identical result every launch), publish ----
    if (blockIdx.x == 0) {
        build_U(w, reinterpret_cast<char*>(v_sm), tid);
        if (tid == 0) { __threadfence(); g_flag = 1; }
        __syncthreads();
    } else {
        // spin only on the very first launch; afterwards a single L2 read
        if (*(volatile int*)&g_flag == 0) {
            while (*(volatile int*)&g_flag == 0) __nanosleep(128);
        }
        __threadfence();
    }

    // --- A fragments: top 16 rows of Whi/Wlo, 4 K-tiles x 4 regs each ---
    uint Ah[4][4], Al[4][4];
    {
        const uint* whi = (const uint*)g_Whi;
        const uint* wlo = (const uint*)g_Wlo;
#pragma unroll
        for (int t = 0; t < 4; t++) {
            int r0 = g, r1 = g + 8;
            int c0 = t * 8 + mm, c1 = c0 + 4;
            Ah[t][0] = whi[r0 * 32 + c0];
            Ah[t][1] = whi[r1 * 32 + c0];
            Ah[t][2] = whi[r0 * 32 + c1];
            Ah[t][3] = whi[r1 * 32 + c1];
            Al[t][0] = wlo[r0 * 32 + c0];
            Al[t][1] = wlo[r1 * 32 + c0];
            Al[t][2] = wlo[r0 * 32 + c1];
            Al[t][3] = wlo[r1 * 32 + c1];
        }
    }

    int comp = -1;
    if (g == 0) comp = 0;
    else if (g == 4) comp = 1;
    else if (g == 2) comp = 2;
    else if (g == 1) comp = 3;

    auto run_tile = [&](int nt, Acc& A) {
        uint Bh[4][2];
        const uint* vb = &v_sm[wrp][nt * 8 + g][0];
#pragma unroll
        for (int t = 0; t < 4; t++) {
            Bh[t][0] = vb[t * 8 + mm];
            Bh[t][1] = vb[t * 8 + mm + 4];
        }
        A.c0 = A.c1 = A.c2 = A.c3 = 0.f;
        A.d0 = A.d1 = A.d2 = A.d3 = 0.f;
#pragma unroll
        for (int t = 0; t < 4; t++) {
            int  src = (t + 2) & 3;
            uint sx  = (t >= 2) ? 0x80000000u : 0u;
            uint p0 = Bh[src][0] ^ sx, p1 = Bh[src][1] ^ sx;
            MMA_TF32(A.c0, A.c1, A.c2, A.c3,
                     Ah[t][0], Ah[t][1], Ah[t][2], Ah[t][3],
                     Bh[t][0], Bh[t][1]);
            MMA_TF32(A.d0, A.d1, A.d2, A.d3,
                     Ah[t][0], Ah[t][1], Ah[t][2], Ah[t][3],
                     p0, p1);
            MMA_TF32(A.c0, A.c1, A.c2, A.c3,
                     Al[t][0], Al[t][1], Al[t][2], Al[t][3],
                     Bh[t][0], Bh[t][1]);
            MMA_TF32(A.d0, A.d1, A.d2, A.d3,
                     Al[t][0], Al[t][1], Al[t][2], Al[t][3],
                     p0, p1);
        }
    };

    auto epilogue = [&](int nt, int Wi, const Acc& A) {
        float pa0 = fmaf(A.c0, A.c0, A.d0 * A.d0);
        float pb0 = fmaf(A.c2, A.c2, A.d2 * A.d2);
        float pa1 = fmaf(A.c1, A.c1, A.d1 * A.d1);
        float pb1 = fmaf(A.c3, A.c3, A.d3 * A.d3);

        float u0 = pa0 + pb0, w0 = pa0 - pb0;
        float u1 = pa1 + pb1, w1 = pa1 - pb1;

#pragma unroll
        for (int r = 0; r < 3; r++) {
            int m = 4 << r;
            float sg = (lane & m) ? -1.f : 1.f;
            float p;
            p = __shfl_xor_sync(0xffffffffu, u0, m); u0 = fmaf(sg, u0, p);
            p = __shfl_xor_sync(0xffffffffu, u1, m); u1 = fmaf(sg, u1, p);
            p = __shfl_xor_sync(0xffffffffu, w0, m); w0 = fmaf(sg, w0, p);
            p = __shfl_xor_sync(0xffffffffu, w1, m); w1 = fmaf(sg, w1, p);
        }

        if (comp >= 0) {
            float v0 = (comp == 0) ? w0 : u0;
            float v1 = (comp == 0) ? w1 : u1;
            int p0 = Wi * 32 + nt * 8 + 2 * mm;
            out[p0 * 4 + comp]       = v0;
            out[(p0 + 1) * 4 + comp] = v1;
        }
    };

    int WiBase = (blockIdx.x * NWARP + wrp) * TITER;
    if (WiBase >= WTOT) return;

    float2 pre[4], nxt[4];
    load_px(x, WiBase * 32 + lane, pre);

#pragma unroll 1
    for (int it = 0; it < TITER; it++) {
        int Wi = WiBase + it;
        if (Wi >= WTOT) break;

        // ---- encode patch Wi*32 + lane from prefetched pixels ----
        {
            float  cth[NQ];
            float2 eph[NQ];
#pragma unroll
            for (int n = 0; n < NQ; n++) {
                float sb, cb, sp, cp;
                __sincosf(1.57079632679489662f * pre[n].x, &sb, &cb);
                __sincosf(3.14159265358979323f * pre[n].y, &sp, &cp);
                cth[n] = cb;
                eph[n] = make_float2(sb * cp, sb * sp);
            }
            float2 ab[4], cd[4];
            ab[0] = make_float2(cth[0] * cth[1], 0.f);
            ab[1] = make_float2(cth[0] * eph[1].x, cth[0] * eph[1].y);
            ab[2] = make_float2(eph[0].x * cth[1], eph[0].y * cth[1]);
            ab[3] = cmul(eph[0], eph[1]);
            cd[0] = make_float2(cth[2] * cth[3], 0.f);
            cd[1] = make_float2(cth[2] * eph[3].x, cth[2] * eph[3].y);
            cd[2] = make_float2(eph[2].x * cth[3], eph[2].y * cth[3]);
            cd[3] = cmul(eph[2], eph[3]);

            float2 psi[16];
#pragma unroll
            for (int i = 0; i < 4; i++)
#pragma unroll
                for (int j = 0; j < 4; j++)
                    psi[i * 4 + j] = cmul(ab[i], cd[j]);

            uint4* vrow = reinterpret_cast<uint4*>(&v_sm[wrp][lane][0]);
#pragma unroll
            for (int q = 0; q < 4; q++)
                vrow[q] = make_uint4(tf32cvt(psi[4*q].x),   tf32cvt(psi[4*q+1].x),
                                     tf32cvt(psi[4*q+2].x), tf32cvt(psi[4*q+3].x));
#pragma unroll
            for (int q = 0; q < 4; q++)
                vrow[4 + q] = make_uint4(tf32cvt(psi[4*q].y),   tf32cvt(psi[4*q+1].y),
                                         tf32cvt(psi[4*q+2].y), tf32cvt(psi[4*q+3].y));
        }
        __syncwarp();

        // prefetch next iteration's pixels (hidden under the nt-loop)
        {
            int WiN = (Wi + 1 < WTOT) ? (Wi + 1) : Wi;
            load_px(x, WiN * 32 + lane, nxt);
        }

        Acc a0, a1;
        run_tile(0, a0);
        run_tile(1, a1);
        epilogue(0, Wi, a0);
        run_tile(2, a0);
        epilogue(1, Wi, a1);
        run_tile(3, a1);
        epilogue(2, Wi, a0);
        epilogue(3, Wi, a1);

        __syncwarp();
        pre[0] = nxt[0]; pre[1] = nxt[1]; pre[2] = nxt[2]; pre[3] = nxt[3];
    }
}

extern "C" void kernel_launch(void* const* d_in, const int* in_sizes, int n_in,
                              void* d_out, int out_size) {
    const float* x = (const float*)d_in[0];
    const float* w = (const float*)d_in[1];
    float* out = (float*)d_out;

    k_qcnn<<<NBLK, NWARP * 32>>>(x, w, out);
}

// round 15
// speedup vs baseline: 1.4922x; 1.4922x over previous
#include <cuda_runtime.h>
#include <cuda_fp16.h>
#include <cstdint>

// QCNN_58025008169535
// x: [32,128,128,3] f32, w: [4,4,3] f32 -> out: [32, 127*127, 4] f32
//
// fp16 tensor-core formulation. amp_re = A0 v, amp_im = A0 v', with
// A0 = [ReU | -ImU] (16x32), v = [Re psi; Im psi], v' = [Im psi; -Re psi].
// fp16 m16n8k16: K=32 = 2 k-tiles; v' = tile-swap + sign flip.
// A split hi/lo in fp16 (2-pass); B single fp16 (same 10-bit mantissa as
// tf32 -> precision unchanged vs R11-R13, mma count halved).

#define DIM 16
#define NQ 4

static constexpr int Bc = 32, Hc = 128, Wc = 128;
static constexpr int PHc = Hc - 1, PWc = Wc - 1;
static constexpr int Pc = PHc * PWc;          // 16129
static constexpr int TOTALc = Bc * Pc;        // 516128
static constexpr int WTOT = TOTALc / 32;      // 16129 warp-iterations
static constexpr int TITER = 2;
static constexpr int NWARP = 4;
static constexpr int NBLK = (WTOT + NWARP * TITER - 1) / (NWARP * TITER);  // 2017

typedef unsigned int uint;

// W as fp16 half2 pairs: [row 0..15][col-pair 0..15]. hi = fp16(W), lo = fp16(W-hi).
__device__ uint g_Whi16[16][16];
__device__ uint g_Wlo16[16][16];

__device__ __forceinline__ float2 cmul(float2 a, float2 b) {
    return make_float2(fmaf(a.x, b.x, -a.y * b.y), fmaf(a.x, b.y, a.y * b.x));
}
__device__ __forceinline__ float2 cadd(float2 a, float2 b) {
    return make_float2(a.x + b.x, a.y + b.y);
}
__device__ __forceinline__ uint h2u(float a, float b) {
    __half2 h = __float22half2_rn(make_float2(a, b));
    return *reinterpret_cast<uint*>(&h);
}

#define MMA_F16(C0, C1, C2, C3, A0, A1, A2, A3, B0, B1)                       \
    asm volatile(                                                             \
        "mma.sync.aligned.m16n8k16.row.col.f32.f16.f16.f32 "                  \
        "{%0,%1,%2,%3}, {%4,%5,%6,%7}, {%8,%9}, {%0,%1,%2,%3};"               \
        : "+f"(C0), "+f"(C1), "+f"(C2), "+f"(C3)                              \
        : "r"(A0), "r"(A1), "r"(A2), "r"(A3), "r"(B0), "r"(B1))

// ---------------------------------------------------------------------------
// Kernel 1 (256 threads): build U, emit W as fp16 hi/lo half2 pairs.
// ---------------------------------------------------------------------------
__global__ void k_build_U(const float* __restrict__ w) {
    __shared__ float2 sg[16][4];
    __shared__ float2 sM[4][DIM][DIM];
    __shared__ float2 sT[2][DIM][DIM];
    __shared__ float2 sU[DIM][DIM];

    int tid = threadIdx.x;

    if (tid < 16) {
        float wx = w[tid * 3 + 0];
        float wy = w[tid * 3 + 1];
        float wz = w[tid * 3 + 2];
        float cx, sx, cy, sy, cz, sz;
        sincosf(0.5f * wx, &sx, &cx);
        sincosf(0.5f * wy, &sy, &cy);
        sincosf(0.5f * wz, &sz, &cz);
        float2 m00 = make_float2(cy * cx,  sy * sx);
        float2 m01 = make_float2(-sy * cx, -cy * sx);
        float2 m10 = make_float2(sy * cx,  -cy * sx);
        float2 m11 = make_float2(cy * cx,  -sy * sx);
        float2 e0 = make_float2(cz, -sz);
        float2 e1 = make_float2(cz,  sz);
        sg[tid][0] = cmul(e0, m00);
        sg[tid][1] = cmul(e0, m01);
        sg[tid][2] = cmul(e1, m10);
        sg[tid][3] = cmul(e1, m11);
    }
    __syncthreads();

#pragma unroll
    for (int r = 0; r < 4; r++) {
        int e = tid + 256 * r;
        int h = e >> 8;
        int st = e & 255;
        int s = st >> 4, t = st & 15;
        float2 prod = make_float2(1.f, 0.f);
#pragma unroll
        for (int q = 0; q < NQ; q++) {
            int sb = (s >> (3 - q)) & 1;
            int tb = (t >> (3 - q)) & 1;
            prod = cmul(prod, sg[h * 4 + q][sb * 2 + tb]);
        }
        bool neg = (((s & 12) == 12) ^ ((s & 3) == 3)) ^ ((s & 6) == 6);
        if (neg) { prod.x = -prod.x; prod.y = -prod.y; }
        sM[h][s][t] = prod;
    }
    __syncthreads();

    {
        int s = tid >> 4, t = tid & 15;
        float2 a1 = make_float2(0.f, 0.f);
        float2 a2 = make_float2(0.f, 0.f);
#pragma unroll
        for (int k = 0; k < DIM; k++) {
            a1 = cadd(a1, cmul(sM[1][s][k], sM[0][k][t]));
            a2 = cadd(a2, cmul(sM[3][s][k], sM[2][k][t]));
        }
        sT[0][s][t] = a1;
        sT[1][s][t] = a2;
    }
    __syncthreads();

    {
        int s = tid >> 4, t = tid & 15;
        float2 u = make_float2(0.f, 0.f);
#pragma unroll
        for (int k = 0; k < DIM; k++)
            u = cadd(u, cmul(sT[1][s][k], sT[0][k][t]));
        sU[s][t] = u;
    }
    __syncthreads();

    // Emit W = [ReU | -ImU] rows as fp16 half2 (hi + residual lo).
    {
        int s = tid >> 4, p = tid & 15;   // row, col-pair
        float v0, v1;
        if (p < 8) { v0 = sU[s][2 * p].x;      v1 = sU[s][2 * p + 1].x; }
        else       { v0 = -sU[s][2 * p - 16].y; v1 = -sU[s][2 * p - 15].y; }
        __half h0 = __float2half_rn(v0);
        __half h1 = __float2half_rn(v1);
        __half l0 = __float2half_rn(v0 - __half2float(h0));
        __half l1 = __float2half_rn(v1 - __half2float(h1));
        __half2 hp = __halves2half2(h0, h1);
        __half2 lp = __halves2half2(l0, l1);
        g_Whi16[s][p] = *reinterpret_cast<uint*>(&hp);
        g_Wlo16[s][p] = *reinterpret_cast<uint*>(&lp);
    }
}

// ---------------------------------------------------------------------------
// Kernel 2: fp16 tensor-core batched matvec.
// ---------------------------------------------------------------------------
struct Acc { float c0, c1, c2, c3, d0, d1, d2, d3; };

__device__ __forceinline__ void load_px(const float* __restrict__ x, int idx,
                                        float2* pre) {
    int b  = idx / Pc;
    int p  = idx - b * Pc;
    int ph = p / PWc;
    int pw = p - ph * PWc;
    const float* base = x + (((b * Hc) + ph) * Wc + pw) * 3;
#pragma unroll
    for (int n = 0; n < 4; n++) {
        int dy = n >> 1, dx = n & 1;
        const float* px = base + (dy * Wc + dx) * 3;
        pre[n] = make_float2(__ldg(px + 1), __ldg(px + 2));
    }
}

__global__ void __launch_bounds__(128, 7)
k_qcnn(const float* __restrict__ x, float* __restrict__ out) {
    // 16 half2 words per patch, padded to 20 (conflict-free for both the
    // STS.128 writes and the 8-row LDS.32 fragment reads).
    __shared__ __align__(16) uint v_sm[NWARP][32][20];   // 10 KB

    int tid  = threadIdx.x;
    int wrp  = tid >> 5;
    int lane = tid & 31;
    int g    = lane >> 2;
    int mm   = lane & 3;

    // --- A fragments: 2 k-tiles x 4 regs, hi and lo ---
    uint Ah[2][4], Al[2][4];
#pragma unroll
    for (int t = 0; t < 2; t++) {
        int p0 = t * 8 + mm, p1 = t * 8 + mm + 4;
        Ah[t][0] = g_Whi16[g][p0];
        Ah[t][1] = g_Whi16[g + 8][p0];
        Ah[t][2] = g_Whi16[g][p1];
        Ah[t][3] = g_Whi16[g + 8][p1];
        Al[t][0] = g_Wlo16[g][p0];
        Al[t][1] = g_Wlo16[g + 8][p0];
        Al[t][2] = g_Wlo16[g][p1];
        Al[t][3] = g_Wlo16[g + 8][p1];
    }

    // WHT destination role: g==0 -> z0 (from w), g==4 -> z1, g==2 -> z2, g==1 -> z3
    int comp = -1;
    if (g == 0) comp = 0;
    else if (g == 4) comp = 1;
    else if (g == 2) comp = 2;
    else if (g == 1) comp = 3;

    auto run_tile = [&](int nt, Acc& A) {
        // B fragments: tile t -> pairs (t*8+mm, t*8+mm+4), n = patch nt*8+g
        const uint* vb = &v_sm[wrp][nt * 8 + g][0];
        uint B0a = vb[mm],     B0b = vb[mm + 4];       // tile 0 (Re)
        uint B1a = vb[8 + mm], B1b = vb[12 + mm];      // tile 1 (Im)
        uint N0a = B0a ^ 0x80008000u, N0b = B0b ^ 0x80008000u;  // -Re

        A.c0 = A.c1 = A.c2 = A.c3 = 0.f;
        A.d0 = A.d1 = A.d2 = A.d3 = 0.f;
        // c = A*[Re;Im] : tile0*B0 + tile1*B1  (hi+lo passes)
        MMA_F16(A.c0, A.c1, A.c2, A.c3, Ah[0][0], Ah[0][1], Ah[0][2], Ah[0][3], B0a, B0b);
        MMA_F16(A.d0, A.d1, A.d2, A.d3, Ah[0][0], Ah[0][1], Ah[0][2], Ah[0][3], B1a, B1b);
        MMA_F16(A.c0, A.c1, A.c2, A.c3, Ah[1][0], Ah[1][1], Ah[1][2], Ah[1][3], B1a, B1b);
        MMA_F16(A.d0, A.d1, A.d2, A.d3, Ah[1][0], Ah[1][1], Ah[1][2], Ah[1][3], N0a, N0b);
        MMA_F16(A.c0, A.c1, A.c2, A.c3, Al[0][0], Al[0][1], Al[0][2], Al[0][3], B0a, B0b);
        MMA_F16(A.d0, A.d1, A.d2, A.d3, Al[0][0], Al[0][1], Al[0][2], Al[0][3], B1a, B1b);
        MMA_F16(A.c0, A.c1, A.c2, A.c3, Al[1][0], Al[1][1], Al[1][2], Al[1][3], B1a, B1b);
        MMA_F16(A.d0, A.d1, A.d2, A.d3, Al[1][0], Al[1][1], Al[1][2], Al[1][3], N0a, N0b);
    };

    auto epilogue = [&](int nt, int Wi, const Acc& A) {
        float pa0 = fmaf(A.c0, A.c0, A.d0 * A.d0);
        float pb0 = fmaf(A.c2, A.c2, A.d2 * A.d2);
        float pa1 = fmaf(A.c1, A.c1, A.d1 * A.d1);
        float pb1 = fmaf(A.c3, A.c3, A.d3 * A.d3);

        float u0 = pa0 + pb0, w0 = pa0 - pb0;
        float u1 = pa1 + pb1, w1 = pa1 - pb1;

#pragma unroll
        for (int r = 0; r < 3; r++) {
            int m = 4 << r;
            float sg = (lane & m) ? -1.f : 1.f;
            float p;
            p = __shfl_xor_sync(0xffffffffu, u0, m); u0 = fmaf(sg, u0, p);
            p = __shfl_xor_sync(0xffffffffu, u1, m); u1 = fmaf(sg, u1, p);
            p = __shfl_xor_sync(0xffffffffu, w0, m); w0 = fmaf(sg, w0, p);
            p = __shfl_xor_sync(0xffffffffu, w1, m); w1 = fmaf(sg, w1, p);
        }

        if (comp >= 0) {
            float v0 = (comp == 0) ? w0 : u0;
            float v1 = (comp == 0) ? w1 : u1;
            int p0 = Wi * 32 + nt * 8 + 2 * mm;
            out[p0 * 4 + comp]       = v0;
            out[(p0 + 1) * 4 + comp] = v1;
        }
    };

    int WiBase = (blockIdx.x * NWARP + wrp) * TITER;
    if (WiBase >= WTOT) return;

    float2 pre[4], nxt[4];
    load_px(x, WiBase * 32 + lane, pre);

#pragma unroll 1
    for (int it = 0; it < TITER; it++) {
        int Wi = WiBase + it;
        if (Wi >= WTOT) break;

        // ---- encode patch Wi*32 + lane, stage psi as fp16 pairs ----
        {
            float  cth[NQ];
            float2 eph[NQ];
#pragma unroll
            for (int n = 0; n < NQ; n++) {
                float sb, cb, sp, cp;
                __sincosf(1.57079632679489662f * pre[n].x, &sb, &cb);
                __sincosf(3.14159265358979323f * pre[n].y, &sp, &cp);
                cth[n] = cb;
                eph[n] = make_float2(sb * cp, sb * sp);
            }
            float2 ab[4], cd[4];
            ab[0] = make_float2(cth[0] * cth[1], 0.f);
            ab[1] = make_float2(cth[0] * eph[1].x, cth[0] * eph[1].y);
            ab[2] = make_float2(eph[0].x * cth[1], eph[0].y * cth[1]);
            ab[3] = cmul(eph[0], eph[1]);
            cd[0] = make_float2(cth[2] * cth[3], 0.f);
            cd[1] = make_float2(cth[2] * eph[3].x, cth[2] * eph[3].y);
            cd[2] = make_float2(eph[2].x * cth[3], eph[2].y * cth[3]);
            cd[3] = cmul(eph[2], eph[3]);

            float2 psi[16];
#pragma unroll
            for (int i = 0; i < 4; i++)
#pragma unroll
                for (int j = 0; j < 4; j++)
                    psi[i * 4 + j] = cmul(ab[i], cd[j]);

            uint4* vrow = reinterpret_cast<uint4*>(&v_sm[wrp][lane][0]);
            // pairs 0-7: Re, pairs 8-15: Im
            vrow[0] = make_uint4(h2u(psi[0].x,  psi[1].x),  h2u(psi[2].x,  psi[3].x),
                                 h2u(psi[4].x,  psi[5].x),  h2u(psi[6].x,  psi[7].x));
            vrow[1] = make_uint4(h2u(psi[8].x,  psi[9].x),  h2u(psi[10].x, psi[11].x),
                                 h2u(psi[12].x, psi[13].x), h2u(psi[14].x, psi[15].x));
            vrow[2] = make_uint4(h2u(psi[0].y,  psi[1].y),  h2u(psi[2].y,  psi[3].y),
                                 h2u(psi[4].y,  psi[5].y),  h2u(psi[6].y,  psi[7].y));
            vrow[3] = make_uint4(h2u(psi[8].y,  psi[9].y),  h2u(psi[10].y, psi[11].y),
                                 h2u(psi[12].y, psi[13].y), h2u(psi[14].y, psi[15].y));
        }
        __syncwarp();

        // prefetch next iteration's pixels
        {
            int WiN = (Wi + 1 < WTOT) ? (Wi + 1) : Wi;
            load_px(x, WiN * 32 + lane, nxt);
        }

        Acc a0, a1;
        run_tile(0, a0);
        run_tile(1, a1);
        epilogue(0, Wi, a0);
        run_tile(2, a0);
        epilogue(1, Wi, a1);
        run_tile(3, a1);
        epilogue(2, Wi, a0);
        epilogue(3, Wi, a1);

        __syncwarp();
        pre[0] = nxt[0]; pre[1] = nxt[1]; pre[2] = nxt[2]; pre[3] = nxt[3];
    }
}

extern "C" void kernel_launch(void* const* d_in, const int* in_sizes, int n_in,
                              void* d_out, int out_size) {
    const float* x = (const float*)d_in[0];
    const float* w = (const float*)d_in[1];
    float* out = (float*)d_out;

    k_build_U<<<1, 256>>>(w);
    k_qcnn<<<NBLK, NWARP * 32>>>(x, out);
}

// round 16
// speedup vs baseline: 1.6684x; 1.1181x over previous
#include <cuda_runtime.h>
#include <cuda_fp16.h>
#include <cstdint>

// QCNN_58025008169535
// x: [32,128,128,3] f32, w: [4,4,3] f32 -> out: [32, 127*127, 4] f32
//
// fp16 tensor-core formulation, TRANSPOSED orientation (R16):
//   C1[patch][state] = V(16x32) x W^T, C2 = V' x W^T  (amp_re / amp_im)
// Patches on the M side, W register-resident on the B side. v' obtained on
// the A side: A'(kt0)=A(kt1) [Im], A'(kt1)=-A(kt0) [-Re].
// Epilogue: state bits b3 (n-tile) and b0 (col) reduce thread-locally;
// only b2b1 (=mm) need a 2-round shfl butterfly -> 12 shfl / 16 patches.

#define DIM 16
#define NQ 4

static constexpr int Bc = 32, Hc = 128, Wc = 128;
static constexpr int PHc = Hc - 1, PWc = Wc - 1;
static constexpr int Pc = PHc * PWc;          // 16129
static constexpr int TOTALc = Bc * Pc;        // 516128
static constexpr int WTOT = TOTALc / 32;      // 16129 warp-iterations
static constexpr int TITER = 2;
static constexpr int NWARP = 4;
static constexpr int NBLK = (WTOT + NWARP * TITER - 1) / (NWARP * TITER);  // 2017

typedef unsigned int uint;

// W as fp16 half2 pairs: [row 0..15][col-pair 0..15]. hi = fp16(W), lo = fp16(W-hi).
__device__ uint g_Whi16[16][16];
__device__ uint g_Wlo16[16][16];

__device__ __forceinline__ float2 cmul(float2 a, float2 b) {
    return make_float2(fmaf(a.x, b.x, -a.y * b.y), fmaf(a.x, b.y, a.y * b.x));
}
__device__ __forceinline__ float2 cadd(float2 a, float2 b) {
    return make_float2(a.x + b.x, a.y + b.y);
}
__device__ __forceinline__ uint h2u(float a, float b) {
    __half2 h = __float22half2_rn(make_float2(a, b));
    return *reinterpret_cast<uint*>(&h);
}

#define MMA_F16(C0, C1, C2, C3, A0, A1, A2, A3, B0, B1)                       \
    asm volatile(                                                             \
        "mma.sync.aligned.m16n8k16.row.col.f32.f16.f16.f32 "                  \
        "{%0,%1,%2,%3}, {%4,%5,%6,%7}, {%8,%9}, {%0,%1,%2,%3};"               \
        : "+f"(C0), "+f"(C1), "+f"(C2), "+f"(C3)                              \
        : "r"(A0), "r"(A1), "r"(A2), "r"(A3), "r"(B0), "r"(B1))

// ---------------------------------------------------------------------------
// Kernel 1 (256 threads): build U, emit W as fp16 hi/lo half2 pairs.
// ---------------------------------------------------------------------------
__global__ void k_build_U(const float* __restrict__ w) {
    __shared__ float2 sg[16][4];
    __shared__ float2 sM[4][DIM][DIM];
    __shared__ float2 sT[2][DIM][DIM];
    __shared__ float2 sU[DIM][DIM];

    int tid = threadIdx.x;

    if (tid < 16) {
        float wx = w[tid * 3 + 0];
        float wy = w[tid * 3 + 1];
        float wz = w[tid * 3 + 2];
        float cx, sx, cy, sy, cz, sz;
        sincosf(0.5f * wx, &sx, &cx);
        sincosf(0.5f * wy, &sy, &cy);
        sincosf(0.5f * wz, &sz, &cz);
        float2 m00 = make_float2(cy * cx,  sy * sx);
        float2 m01 = make_float2(-sy * cx, -cy * sx);
        float2 m10 = make_float2(sy * cx,  -cy * sx);
        float2 m11 = make_float2(cy * cx,  -sy * sx);
        float2 e0 = make_float2(cz, -sz);
        float2 e1 = make_float2(cz,  sz);
        sg[tid][0] = cmul(e0, m00);
        sg[tid][1] = cmul(e0, m01);
        sg[tid][2] = cmul(e1, m10);
        sg[tid][3] = cmul(e1, m11);
    }
    __syncthreads();

#pragma unroll
    for (int r = 0; r < 4; r++) {
        int e = tid + 256 * r;
        int h = e >> 8;
        int st = e & 255;
        int s = st >> 4, t = st & 15;
        float2 prod = make_float2(1.f, 0.f);
#pragma unroll
        for (int q = 0; q < NQ; q++) {
            int sb = (s >> (3 - q)) & 1;
            int tb = (t >> (3 - q)) & 1;
            prod = cmul(prod, sg[h * 4 + q][sb * 2 + tb]);
        }
        bool neg = (((s & 12) == 12) ^ ((s & 3) == 3)) ^ ((s & 6) == 6);
        if (neg) { prod.x = -prod.x; prod.y = -prod.y; }
        sM[h][s][t] = prod;
    }
    __syncthreads();

    {
        int s = tid >> 4, t = tid & 15;
        float2 a1 = make_float2(0.f, 0.f);
        float2 a2 = make_float2(0.f, 0.f);
#pragma unroll
        for (int k = 0; k < DIM; k++) {
            a1 = cadd(a1, cmul(sM[1][s][k], sM[0][k][t]));
            a2 = cadd(a2, cmul(sM[3][s][k], sM[2][k][t]));
        }
        sT[0][s][t] = a1;
        sT[1][s][t] = a2;
    }
    __syncthreads();

    {
        int s = tid >> 4, t = tid & 15;
        float2 u = make_float2(0.f, 0.f);
#pragma unroll
        for (int k = 0; k < DIM; k++)
            u = cadd(u, cmul(sT[1][s][k], sT[0][k][t]));
        sU[s][t] = u;
    }
    __syncthreads();

    // Emit W = [ReU | -ImU] rows as fp16 half2 (hi + residual lo).
    {
        int s = tid >> 4, p = tid & 15;   // row, col-pair
        float v0, v1;
        if (p < 8) { v0 = sU[s][2 * p].x;      v1 = sU[s][2 * p + 1].x; }
        else       { v0 = -sU[s][2 * p - 16].y; v1 = -sU[s][2 * p - 15].y; }
        __half h0 = __float2half_rn(v0);
        __half h1 = __float2half_rn(v1);
        __half l0 = __float2half_rn(v0 - __half2float(h0));
        __half l1 = __float2half_rn(v1 - __half2float(h1));
        __half2 hp = __halves2half2(h0, h1);
        __half2 lp = __halves2half2(l0, l1);
        g_Whi16[s][p] = *reinterpret_cast<uint*>(&hp);
        g_Wlo16[s][p] = *reinterpret_cast<uint*>(&lp);
    }
}

// ---------------------------------------------------------------------------
// Kernel 2: transposed fp16 tensor-core batched matvec.
// ---------------------------------------------------------------------------
__device__ __forceinline__ void load_px(const float* __restrict__ x, int idx,
                                        float2* pre) {
    int b  = idx / Pc;
    int p  = idx - b * Pc;
    int ph = p / PWc;
    int pw = p - ph * PWc;
    const float* base = x + (((b * Hc) + ph) * Wc + pw) * 3;
#pragma unroll
    for (int n = 0; n < 4; n++) {
        int dy = n >> 1, dx = n & 1;
        const float* px = base + (dy * Wc + dx) * 3;
        pre[n] = make_float2(__ldg(px + 1), __ldg(px + 2));
    }
}

__global__ void __launch_bounds__(128, 7)
k_qcnn(const float* __restrict__ x, float* __restrict__ out) {
    __shared__ __align__(16) uint v_sm[NWARP][32][20];   // 10 KB

    int tid  = threadIdx.x;
    int wrp  = tid >> 5;
    int lane = tid & 31;
    int g    = lane >> 2;
    int mm   = lane & 3;

    // --- B fragments (W), persistent: [nt][kt][2 regs] ---
    // B col n = nt*8+g -> W row; b0: k-pair kt*8+mm, b1: kt*8+mm+4
    uint Bh[2][2][2], Bl[2][2][2];
#pragma unroll
    for (int nt = 0; nt < 2; nt++)
#pragma unroll
        for (int kt = 0; kt < 2; kt++) {
            Bh[nt][kt][0] = g_Whi16[nt * 8 + g][kt * 8 + mm];
            Bh[nt][kt][1] = g_Whi16[nt * 8 + g][kt * 8 + mm + 4];
            Bl[nt][kt][0] = g_Wlo16[nt * 8 + g][kt * 8 + mm];
            Bl[nt][kt][1] = g_Wlo16[nt * 8 + g][kt * 8 + mm + 4];
        }

    int WiBase = (blockIdx.x * NWARP + wrp) * TITER;
    if (WiBase >= WTOT) return;

    float2 pre[4], nxt[4];
    load_px(x, WiBase * 32 + lane, pre);

#pragma unroll 1
    for (int it = 0; it < TITER; it++) {
        int Wi = WiBase + it;
        if (Wi >= WTOT) break;

        // ---- encode patch Wi*32 + lane, stage psi as fp16 pairs ----
        {
            float  cth[NQ];
            float2 eph[NQ];
#pragma unroll
            for (int n = 0; n < NQ; n++) {
                float sb, cb, sp, cp;
                __sincosf(1.57079632679489662f * pre[n].x, &sb, &cb);
                __sincosf(3.14159265358979323f * pre[n].y, &sp, &cp);
                cth[n] = cb;
                eph[n] = make_float2(sb * cp, sb * sp);
            }
            float2 ab[4], cd[4];
            ab[0] = make_float2(cth[0] * cth[1], 0.f);
            ab[1] = make_float2(cth[0] * eph[1].x, cth[0] * eph[1].y);
            ab[2] = make_float2(eph[0].x * cth[1], eph[0].y * cth[1]);
            ab[3] = cmul(eph[0], eph[1]);
            cd[0] = make_float2(cth[2] * cth[3], 0.f);
            cd[1] = make_float2(cth[2] * eph[3].x, cth[2] * eph[3].y);
            cd[2] = make_float2(eph[2].x * cth[3], eph[2].y * cth[3]);
            cd[3] = cmul(eph[2], eph[3]);

            float2 psi[16];
#pragma unroll
            for (int i = 0; i < 4; i++)
#pragma unroll
                for (int j = 0; j < 4; j++)
                    psi[i * 4 + j] = cmul(ab[i], cd[j]);

            uint4* vrow = reinterpret_cast<uint4*>(&v_sm[wrp][lane][0]);
            // pairs 0-7: Re(psi0..15), pairs 8-15: Im
            vrow[0] = make_uint4(h2u(psi[0].x,  psi[1].x),  h2u(psi[2].x,  psi[3].x),
                                 h2u(psi[4].x,  psi[5].x),  h2u(psi[6].x,  psi[7].x));
            vrow[1] = make_uint4(h2u(psi[8].x,  psi[9].x),  h2u(psi[10].x, psi[11].x),
                                 h2u(psi[12].x, psi[13].x), h2u(psi[14].x, psi[15].x));
            vrow[2] = make_uint4(h2u(psi[0].y,  psi[1].y),  h2u(psi[2].y,  psi[3].y),
                                 h2u(psi[4].y,  psi[5].y),  h2u(psi[6].y,  psi[7].y));
            vrow[3] = make_uint4(h2u(psi[8].y,  psi[9].y),  h2u(psi[10].y, psi[11].y),
                                 h2u(psi[12].y, psi[13].y), h2u(psi[14].y, psi[15].y));
        }
        __syncwarp();

        // prefetch next iteration's pixels
        {
            int WiN = (Wi + 1 < WTOT) ? (Wi + 1) : Wi;
            load_px(x, WiN * 32 + lane, nxt);
        }

        // ---- 2 M-groups of 16 patches ----
#pragma unroll
        for (int mg = 0; mg < 2; mg++) {
            // A fragments: rows = patches mg*16 + {g, g+8}
            const uint* va0 = &v_sm[wrp][mg * 16 + g][0];
            const uint* va1 = &v_sm[wrp][mg * 16 + g + 8][0];
            uint A0a = va0[mm],     A0b = va1[mm];        // tile0 (Re), k 2mm
            uint A0c = va0[mm + 4], A0d = va1[mm + 4];    //             k 2mm+8
            uint A1a = va0[8 + mm],     A1b = va1[8 + mm];       // tile1 (Im)
            uint A1c = va0[8 + mm + 4], A1d = va1[8 + mm + 4];
            uint N0a = A0a ^ 0x80008000u, N0b = A0b ^ 0x80008000u;  // -Re
            uint N0c = A0c ^ 0x80008000u, N0d = A0d ^ 0x80008000u;

            float e0 = 0.f, e1 = 0.f, e2 = 0.f, e3 = 0.f;   // C1 nt0 (re, s 0-7)
            float f0 = 0.f, f1 = 0.f, f2 = 0.f, f3 = 0.f;   // C1 nt1 (re, s 8-15)
            float h0 = 0.f, h1 = 0.f, h2 = 0.f, h3 = 0.f;   // C2 nt0 (im)
            float i0 = 0.f, i1 = 0.f, i2 = 0.f, i3 = 0.f;   // C2 nt1 (im)

            // C1[nt] = A(kt0)*B[nt][0] + A(kt1)*B[nt][1]  (hi + lo)
            MMA_F16(e0, e1, e2, e3, A0a, A0b, A0c, A0d, Bh[0][0][0], Bh[0][0][1]);
            MMA_F16(h0, h1, h2, h3, A1a, A1b, A1c, A1d, Bh[0][0][0], Bh[0][0][1]);
            MMA_F16(e0, e1, e2, e3, A1a, A1b, A1c, A1d, Bh[0][1][0], Bh[0][1][1]);
            MMA_F16(h0, h1, h2, h3, N0a, N0b, N0c, N0d, Bh[0][1][0], Bh[0][1][1]);
            MMA_F16(f0, f1, f2, f3, A0a, A0b, A0c, A0d, Bh[1][0][0], Bh[1][0][1]);
            MMA_F16(i0, i1, i2, i3, A1a, A1b, A1c, A1d, Bh[1][0][0], Bh[1][0][1]);
            MMA_F16(f0, f1, f2, f3, A1a, A1b, A1c, A1d, Bh[1][1][0], Bh[1][1][1]);
            MMA_F16(i0, i1, i2, i3, N0a, N0b, N0c, N0d, Bh[1][1][0], Bh[1][1][1]);
            MMA_F16(e0, e1, e2, e3, A0a, A0b, A0c, A0d, Bl[0][0][0], Bl[0][0][1]);
            MMA_F16(h0, h1, h2, h3, A1a, A1b, A1c, A1d, Bl[0][0][0], Bl[0][0][1]);
            MMA_F16(e0, e1, e2, e3, A1a, A1b, A1c, A1d, Bl[0][1][0], Bl[0][1][1]);
            MMA_F16(h0, h1, h2, h3, N0a, N0b, N0c, N0d, Bl[0][1][0], Bl[0][1][1]);
            MMA_F16(f0, f1, f2, f3, A0a, A0b, A0c, A0d, Bl[1][0][0], Bl[1][0][1]);
            MMA_F16(i0, i1, i2, i3, A1a, A1b, A1c, A1d, Bl[1][0][0], Bl[1][0][1]);
            MMA_F16(f0, f1, f2, f3, A1a, A1b, A1c, A1d, Bl[1][1][0], Bl[1][1][1]);
            MMA_F16(i0, i1, i2, i3, N0a, N0b, N0c, N0d, Bl[1][1][0], Bl[1][1][1]);

            // ---- epilogue ----
            // patch P0 = row g: cols (2mm, 2mm+1) of each n-tile
            float p00 = fmaf(e0, e0, h0 * h0);   // s = 2mm     (nt0, c0)
            float p01 = fmaf(e1, e1, h1 * h1);   // s = 2mm+1   (nt0, c1)
            float p10 = fmaf(f0, f0, i0 * i0);   // s = 8+2mm   (nt1, c0)
            float p11 = fmaf(f1, f1, i1 * i1);   // s = 8+2mm+1 (nt1, c1)
            // patch P1 = row g+8
            float q00 = fmaf(e2, e2, h2 * h2);
            float q01 = fmaf(e3, e3, h3 * h3);
            float q10 = fmaf(f2, f2, i2 * i2);
            float q11 = fmaf(f3, f3, i3 * i3);

            // local combos: b3 (nt) and b0 (c) reduce in-thread
            float pt0 = p00 + p01, pt1 = p10 + p11;
            float S_a  = pt0 + pt1;                      // for z1/z2 (signs in mm)
            float Z0_a = pt0 - pt1;                      // b3-signed
            float Z3_a = (p00 - p01) + (p10 - p11);      // b0-signed
            float qt0 = q00 + q01, qt1 = q10 + q11;
            float S_b  = qt0 + qt1;
            float Z0_b = qt0 - qt1;
            float Z3_b = (q00 - q01) + (q10 - q11);

            // 2-round WHT butterfly over lane bits {1,2} (the mm bits)
#pragma unroll
            for (int r = 0; r < 2; r++) {
                int m = 1 << r;
                float sg = (lane & m) ? -1.f : 1.f;
                float p;
                p = __shfl_xor_sync(0xffffffffu, S_a,  m); S_a  = fmaf(sg, S_a,  p);
                p = __shfl_xor_sync(0xffffffffu, Z0_a, m); Z0_a = fmaf(sg, Z0_a, p);
                p = __shfl_xor_sync(0xffffffffu, Z3_a, m); Z3_a = fmaf(sg, Z3_a, p);
                p = __shfl_xor_sync(0xffffffffu, S_b,  m); S_b  = fmaf(sg, S_b,  p);
                p = __shfl_xor_sync(0xffffffffu, Z0_b, m); Z0_b = fmaf(sg, Z0_b, p);
                p = __shfl_xor_sync(0xffffffffu, Z3_b, m); Z3_b = fmaf(sg, Z3_b, p);
            }

            // mm=0: plain sums -> z0 (Z0), z3 (Z3); mm=2: z1 (S, b2=lane bit1);
            // mm=1: z2 (S, b1=lane bit0)
            int P0 = Wi * 32 + mg * 16 + g;
            int P1 = P0 + 8;
            if (mm == 0) {
                out[P0 * 4 + 0] = Z0_a;  out[P0 * 4 + 3] = Z3_a;
                out[P1 * 4 + 0] = Z0_b;  out[P1 * 4 + 3] = Z3_b;
            } else if (mm == 2) {
                out[P0 * 4 + 1] = S_a;   out[P1 * 4 + 1] = S_b;
            } else if (mm == 1) {
                out[P0 * 4 + 2] = S_a;   out[P1 * 4 + 2] = S_b;
            }
        }

        __syncwarp();
        pre[0] = nxt[0]; pre[1] = nxt[1]; pre[2] = nxt[2]; pre[3] = nxt[3];
    }
}

extern "C" void kernel_launch(void* const* d_in, const int* in_sizes, int n_in,
                              void* d_out, int out_size) {
    const float* x = (const float*)d_in[0];
    const float* w = (const float*)d_in[1];
    float* out = (float*)d_out;

    k_build_U<<<1, 256>>>(w);
    k_qcnn<<<NBLK, NWARP * 32>>>(x, out);
}